// round 15
// baseline (speedup 1.0000x reference)
#include <cuda_runtime.h>
#include <cuda_fp16.h>
#include <math.h>
#include <stdint.h>

// Problem constants
#define B_     16
#define S_     512
#define D_     768
#define H_     12
#define DH_    64
#define L_     12
#define FF_    3072
#define VOCAB_ 40990
#define BS_    (B_ * S_)     // 8192 rows
#define D3_    (3 * D_)      // 2304

// ---------------------------------------------------------------------------
// Scratch (static device globals: allocation-free, graph-capturable)
// ---------------------------------------------------------------------------
__device__ __half g_qkv[(size_t)BS_ * D3_];   // fp16 qkv (attention input)
__device__ __half g_attn[(size_t)BS_ * D_];   // attention out (fp16, proj A)
__device__ float  g_r1[(size_t)BS_ * D_];
__device__ float  g_n[(size_t)BS_ * D_];
__device__ __half g_nr[(size_t)BS_ * D_];     // fp16 n (fc A)
__device__ __half g_hr[(size_t)BS_ * D_];     // fp16 h (qkv A)
__device__ __half g_ff[(size_t)BS_ * FF_];    // fp16 gelu out (mlp A)
__device__ float  g_p2[2 * (size_t)BS_ * D_]; // mlp split-K partials (fp32)
// Transposed ([N,K]) fp16 weight copies
__device__ __half g_caw_t[(size_t)L_ * D3_ * D_];
__device__ __half g_apw_t[(size_t)L_ * D_ * D_];
__device__ __half g_fcw_t[(size_t)L_ * FF_ * D_];
__device__ __half g_mpw_t[(size_t)L_ * D_ * FF_];

// ---------------------------------------------------------------------------
// Helpers
// ---------------------------------------------------------------------------
__device__ __forceinline__ uint32_t smem_u32(const void* p) {
    uint32_t a;
    asm("{ .reg .u64 t; cvta.to.shared.u64 t, %1; cvt.u32.u64 %0, t; }"
        : "=r"(a) : "l"(p));
    return a;
}
__device__ __forceinline__ void mma_f16(float c[4], const unsigned a[4],
                                        const unsigned b[2]) {
    asm volatile(
        "mma.sync.aligned.m16n8k16.row.col.f32.f16.f16.f32 "
        "{%0,%1,%2,%3},{%4,%5,%6,%7},{%8,%9},{%0,%1,%2,%3};"
        : "+f"(c[0]), "+f"(c[1]), "+f"(c[2]), "+f"(c[3])
        : "r"(a[0]), "r"(a[1]), "r"(a[2]), "r"(a[3]), "r"(b[0]), "r"(b[1]));
}
__device__ __forceinline__ void cp16(unsigned smem_addr, const void* gptr) {
    asm volatile("cp.async.cg.shared.global [%0], [%1], 16;\n"
                 :: "r"(smem_addr), "l"(gptr));
}
#define LDSM4(r0, r1, r2, r3, addr) \
    asm volatile("ldmatrix.sync.aligned.m8n8.x4.shared.b16 {%0,%1,%2,%3}, [%4];" \
        : "=r"(r0), "=r"(r1), "=r"(r2), "=r"(r3) : "r"(addr))
#define LDSM4T(r0, r1, r2, r3, addr) \
    asm volatile("ldmatrix.sync.aligned.m8n8.x4.trans.shared.b16 {%0,%1,%2,%3}, [%4];" \
        : "=r"(r0), "=r"(r1), "=r"(r2), "=r"(r3) : "r"(addr))

// Fast GELU: tanh(i) = 1 - 2/(e^{2i}+1); saturates correctly, no NaN path.
__device__ __forceinline__ float gelu_fast(float v) {
    float i = 0.7978845608028654f * (v + 0.044715f * v * v * v);
    float t = 1.0f - 2.0f / (__expf(2.0f * i) + 1.0f);
    return 0.5f * v * (1.0f + t);
}

// ---------------------------------------------------------------------------
// prep_kernel: one launch covering embedding + all 4 weight transposes.
// ---------------------------------------------------------------------------
#define NB_EMBED 8192
#define NB_CAW   ((D3_ / 32) * (D_ / 32) * L_)   // 20736
#define NB_APW   ((D_ / 32) * (D_ / 32) * L_)    // 6912
#define NB_FCW   ((FF_ / 32) * (D_ / 32) * L_)   // 27648
#define NB_MPW   ((D_ / 32) * (FF_ / 32) * L_)   // 27648
#define NB_PREP  (NB_EMBED + NB_CAW + NB_APW + NB_FCW + NB_MPW)

__device__ __forceinline__ void do_transpose(
    const float* __restrict__ W, __half* __restrict__ Wt,
    int K, int N, int bid, float (*t)[33])
{
    const int nbx = N / 32, nby = K / 32;
    const int per_l = nbx * nby;
    const int l = bid / per_l, rem = bid - l * per_l;
    const int bx = rem % nbx, by = rem / nbx;
    const float* Wl = W + (size_t)l * K * N;
    __half* Wtl = Wt + (size_t)l * K * N;
    const int nb = bx * 32, kb = by * 32;
    const int tid = threadIdx.x;
    const int tx = tid & 31, ty = tid >> 5;
    #pragma unroll
    for (int j = 0; j < 32; j += 8)
        t[ty + j][tx] = Wl[(size_t)(kb + ty + j) * N + nb + tx];
    __syncthreads();
    #pragma unroll
    for (int j = 0; j < 2; j++) {
        int n = (tid >> 4) + j * 16;
        int c = tid & 15;
        __half2 v = __floats2half2_rn(t[2 * c][n], t[2 * c + 1][n]);
        *(__half2*)&Wtl[(size_t)(nb + n) * K + kb + 2 * c] = v;
    }
}

__global__ __launch_bounds__(256) void prep_kernel(
    const void* __restrict__ x, const float* __restrict__ we,
    float* __restrict__ out, __half* __restrict__ outh,
    const float* __restrict__ caw, __half* __restrict__ cawT,
    const float* __restrict__ apw, __half* __restrict__ apwT,
    const float* __restrict__ fcw, __half* __restrict__ fcwT,
    const float* __restrict__ mpw, __half* __restrict__ mpwT)
{
    __shared__ float t[32][33];
    __shared__ int is64;
    int b = blockIdx.x;

    if (b < NB_EMBED) {
        if (threadIdx.x == 0) {
            const unsigned long long* p = (const unsigned long long*)x;
            int ok = 1;
            #pragma unroll 1
            for (int i = 0; i < 64; i++)
                if (p[i] >= (unsigned long long)VOCAB_) { ok = 0; break; }
            is64 = ok;
        }
        __syncthreads();
        long long i0, i1;
        if (is64) {
            const long long* p = (const long long*)x;
            i0 = p[2 * b]; i1 = p[2 * b + 1];
        } else {
            const int* p = (const int*)x;
            i0 = p[2 * b]; i1 = p[2 * b + 1];
        }
        const float* w0 = we + (size_t)i0 * D_;
        const float* w1 = we + (size_t)i1 * D_;
        float* o = out + (size_t)b * D_;
        __half* oh = outh + (size_t)b * D_;
        for (int c = threadIdx.x; c < D_; c += 256) {
            float v = w0[c] + w1[c];
            o[c] = v;
            oh[c] = __float2half_rn(v);
        }
        return;
    }
    b -= NB_EMBED;
    if (b < NB_CAW) { do_transpose(caw, cawT, D_, D3_, b, t); return; }
    b -= NB_CAW;
    if (b < NB_APW) { do_transpose(apw, apwT, D_, D_, b, t); return; }
    b -= NB_APW;
    if (b < NB_FCW) { do_transpose(fcw, fcwT, D_, FF_, b, t); return; }
    b -= NB_FCW;
    do_transpose(mpw, mpwT, FF_, D_, b, t);
}

// ---------------------------------------------------------------------------
// FP16 MMA GEMM, shape-tuned thread count (both variants bench-validated):
//   TPB=256: 8 warps, warp tile 32x64 (higher MACs/smem-byte; best for the
//            2-wave N=768 GEMMs: proj, mlp split-K)
//   TPB=512: 16 warps, warp tile 32x32 (more latency hiding; best for the
//            deep-wave GEMMs: qkv N=2304, fc N=3072)
// CTA tile 128x128x64, 3-stage cp.async pipeline, ldmatrix fragments, fp32
// accumulate/epilogue. Per-output arithmetic identical in both variants.
// C[M,N] = A[M,K] @ Bt[N,K]^T (+bias)(+res)(gelu).
// SPLITK: blockIdx.z selects a K-half (caller passes K = K_orig/2; operand
// row stride is 2K); partial written to C + z*M*N, no bias/res.
// ---------------------------------------------------------------------------
#define RSH     72                       // row stride in halves
#define OPB     (128 * RSH * 2)          // bytes per operand per stage (18432)
#define STGB    (2 * OPB)                // bytes per stage (36864)
#define NSTG    3
#define GEMM_SMEM (NSTG * STGB)          // 110592 bytes

template<int TPB, bool BIAS, bool RES, bool DOGELU, bool HALFOUT, bool SPLITK>
__global__ __launch_bounds__(TPB, 2) void mma_gemm_kernel(
    const __half* __restrict__ A, const __half* __restrict__ Bt,
    const float* __restrict__ bias, const float* __restrict__ res,
    void* __restrict__ Cv, int M, int N, int K)
{
    constexpr int WN   = (TPB == 256) ? 64 : 32;  // warp tile n-width
    constexpr int NJ   = WN / 8;                  // n8 tiles per warp
    constexpr int NQ   = WN / 16;                 // B LDSM4s per k16 step
    constexpr int NWN  = 128 / WN;                // warp_n slots
    constexpr int RPI  = TPB / 8;                 // fill rows per iteration
    constexpr int FIT  = 128 / RPI;               // fill iterations per operand

    extern __shared__ char smem[];
    const int lda = SPLITK ? (K << 1) : K;   // operand row stride
    if (SPLITK) {
        const int kz = blockIdx.z;
        A  += (size_t)kz * K;
        Bt += (size_t)kz * K;
        Cv = (void*)((float*)Cv + (size_t)kz * M * N);
    }

    const int tid  = threadIdx.x;
    const int lane = tid & 31;
    const int wid  = tid >> 5;
    const int gid  = lane >> 2;
    const int tig  = lane & 3;
    const int warp_m = wid / NWN;       // 0..3 -> 32-row slab
    const int warp_n = wid % NWN;       // -> WN-col slab
    const int bm = blockIdx.y * 128, bn = blockIdx.x * 128;

    const __half* Arow = A + (size_t)bm * lda;
    const __half* Brow = Bt + (size_t)bn * lda;

    const int frow = tid >> 3;
    const int fcol = (tid & 7) * 8;

    auto load_stage = [&](int s, int ic) {
        char* As = smem + s * STGB;
        char* Bs = As + OPB;
        const int k0 = ic << 6;
        #pragma unroll
        for (int h = 0; h < FIT; h++) {
            int r = h * RPI + frow;
            cp16((unsigned)__cvta_generic_to_shared(As + (r * RSH + fcol) * 2),
                 Arow + (size_t)r * lda + k0 + fcol);
        }
        #pragma unroll
        for (int h = 0; h < FIT; h++) {
            int r = h * RPI + frow;
            cp16((unsigned)__cvta_generic_to_shared(Bs + (r * RSH + fcol) * 2),
                 Brow + (size_t)r * lda + k0 + fcol);
        }
        asm volatile("cp.async.commit_group;" ::: "memory");
    };

    float acc[2][NJ][4];
    #pragma unroll
    for (int i = 0; i < 2; i++)
        #pragma unroll
        for (int j = 0; j < NJ; j++)
            #pragma unroll
            for (int c = 0; c < 4; c++) acc[i][j][c] = 0.f;

    const uint32_t sbase = smem_u32(smem);
    const uint32_t aoff =
        (uint32_t)(warp_m * 32 + (lane & 15)) * (RSH * 2) + ((lane >> 4) << 4);
    const uint32_t boff =
        (uint32_t)(warp_n * WN + (lane & 7) + ((lane >> 4) << 3)) * (RSH * 2)
        + (((lane >> 3) & 1) << 4);

    const int NK = K >> 6;
    load_stage(0, 0);
    load_stage(1, 1);

    for (int it = 0; it < NK; it++) {
        if (it + 1 < NK)
            asm volatile("cp.async.wait_group 1;" ::: "memory");
        else
            asm volatile("cp.async.wait_group 0;" ::: "memory");
        __syncthreads();
        if (it + 2 < NK) load_stage((it + 2) % NSTG, it + 2);

        const uint32_t sA = sbase + (uint32_t)((it % NSTG) * STGB);
        const uint32_t sB = sA + OPB;

        #pragma unroll
        for (int ks = 0; ks < 4; ks++) {
            const uint32_t kb = ks * 32;
            unsigned a[2][4];
            LDSM4(a[0][0], a[0][1], a[0][2], a[0][3], sA + aoff + kb);
            LDSM4(a[1][0], a[1][1], a[1][2], a[1][3],
                  sA + aoff + 16u * (RSH * 2) + kb);
            unsigned b[NJ][2];
            #pragma unroll
            for (int q = 0; q < NQ; q++)
                LDSM4(b[2 * q][0], b[2 * q][1], b[2 * q + 1][0], b[2 * q + 1][1],
                      sB + boff + (uint32_t)(q * 16 * (RSH * 2)) + kb);
            #pragma unroll
            for (int im = 0; im < 2; im++)
                #pragma unroll
                for (int j = 0; j < NJ; j++)
                    mma_f16(acc[im][j], a[im], b[j]);
        }
    }

    float* Cf = (float*)Cv;
    __half* Ch = (__half*)Cv;
    #pragma unroll
    for (int im = 0; im < 2; im++) {
        #pragma unroll
        for (int j = 0; j < NJ; j++) {
            int r = bm + warp_m * 32 + im * 16 + gid;
            int c = bn + warp_n * WN + j * 8 + tig * 2;
            #pragma unroll
            for (int half_ = 0; half_ < 2; half_++) {
                int rr = r + half_ * 8;
                float v0 = acc[im][j][half_ * 2 + 0];
                float v1 = acc[im][j][half_ * 2 + 1];
                if (BIAS) { v0 += bias[c]; v1 += bias[c + 1]; }
                if (RES) {
                    const float* rp = res + (size_t)rr * N + c;
                    v0 += rp[0]; v1 += rp[1];
                }
                if (DOGELU) {
                    v0 = gelu_fast(v0);
                    v1 = gelu_fast(v1);
                }
                if (HALFOUT) {
                    *(__half2*)(Ch + (size_t)rr * N + c) =
                        __floats2half2_rn(v0, v1);
                } else {
                    *(float2*)(Cf + (size_t)rr * N + c) = make_float2(v0, v1);
                }
            }
        }
    }
}

// ---------------------------------------------------------------------------
// Tensor-core fp16 flash attention (64-q blocks, 4 warps, 4 CTAs/SM,
// heavy q-tiles first).
// ---------------------------------------------------------------------------
#define ASTR 72   // smem row stride in halves (144B)

__global__ __launch_bounds__(128, 4) void attn_kernel(
    const __half* __restrict__ qkv, __half* __restrict__ out)
{
    __shared__ __half Qs[64 * ASTR];          // 9216 B
    __shared__ __half KVs[2][2][64 * ASTR];   // 36864 B  [buf][K=0/V=1]

    const int tid = threadIdx.x, lane = tid & 31, w = tid >> 5;
    const int gid = lane >> 2, tig = lane & 3;
    const int qt = (int)gridDim.x - 1 - (int)blockIdx.x;   // heavy tiles first
    const int head = blockIdx.y, batch = blockIdx.z;
    const int qbase = qt * 64;
    const __half* base = qkv + (size_t)batch * S_ * D3_;
    const int hd = head * DH_;

    #pragma unroll
    for (int i = 0; i < 4; i++) {
        int id = tid + i * 128;
        int r = id >> 3, c = (id & 7) * 8;
        cp16(smem_u32(Qs + r * ASTR + c),
             base + (size_t)(qbase + r) * D3_ + hd + c);
    }

    auto load_kv = [&](int buf, int kt) {
        #pragma unroll
        for (int i = 0; i < 4; i++) {
            int id = tid + i * 128;
            int r = id >> 3, c = (id & 7) * 8;
            const __half* krow = base + (size_t)(kt * 64 + r) * D3_;
            cp16(smem_u32(&KVs[buf][0][r * ASTR + c]), krow + D_ + hd + c);
            cp16(smem_u32(&KVs[buf][1][r * ASTR + c]), krow + 2 * D_ + hd + c);
        }
        asm volatile("cp.async.commit_group;" ::: "memory");
    };

    const int ntk = qt + 1;
    load_kv(0, 0);
    asm volatile("cp.async.wait_group 0;" ::: "memory");
    __syncthreads();

    unsigned qf[4][4];
    {
        const uint32_t qaddr = smem_u32(Qs)
            + (uint32_t)(w * 16 + (lane & 15)) * (ASTR * 2) + ((lane >> 4) << 4);
        #pragma unroll
        for (int ks = 0; ks < 4; ks++)
            LDSM4(qf[ks][0], qf[ks][1], qf[ks][2], qf[ks][3], qaddr + 32 * ks);
        const __half2 sc = __float2half2_rn(0.125f);
        #pragma unroll
        for (int ks = 0; ks < 4; ks++)
            #pragma unroll
            for (int i = 0; i < 4; i++) {
                __half2 h = *(__half2*)&qf[ks][i];
                h = __hmul2(h, sc);
                qf[ks][i] = *(unsigned*)&h;
            }
    }

    float m0 = -1e30f, m1 = -1e30f, l0 = 0.f, l1 = 0.f;
    float o[8][4];
    #pragma unroll
    for (int j = 0; j < 8; j++)
        #pragma unroll
        for (int c = 0; c < 4; c++) o[j][c] = 0.f;

    for (int kt = 0; kt < ntk; kt++) {
        const int buf = kt & 1;
        if (kt > 0) {
            asm volatile("cp.async.wait_group 0;" ::: "memory");
            __syncthreads();
        }
        if (kt + 1 < ntk) load_kv(buf ^ 1, kt + 1);

        float s[8][4];
        #pragma unroll
        for (int j = 0; j < 8; j++)
            #pragma unroll
            for (int c = 0; c < 4; c++) s[j][c] = 0.f;

        const uint32_t kaddr = smem_u32(&KVs[buf][0][0])
            + (uint32_t)((lane & 7) + ((lane >> 4) << 3)) * (ASTR * 2)
            + (((lane >> 3) & 1) << 4);
        #pragma unroll
        for (int ks = 0; ks < 4; ks++) {
            unsigned b[8][2];
            #pragma unroll
            for (int q = 0; q < 4; q++)
                LDSM4(b[2 * q][0], b[2 * q][1], b[2 * q + 1][0], b[2 * q + 1][1],
                      kaddr + (uint32_t)(q * 16 * (ASTR * 2)) + 32 * ks);
            #pragma unroll
            for (int j = 0; j < 8; j++)
                mma_f16(s[j], qf[ks], b[j]);
        }

        if (kt == qt) {
            const int rA = w * 16 + gid;
            #pragma unroll
            for (int j = 0; j < 8; j++) {
                int c0 = j * 8 + tig * 2, c1 = c0 + 1;
                if (c0 > rA)     s[j][0] = -1e30f;
                if (c1 > rA)     s[j][1] = -1e30f;
                if (c0 > rA + 8) s[j][2] = -1e30f;
                if (c1 > rA + 8) s[j][3] = -1e30f;
            }
        }

        float mx0 = -1e30f, mx1 = -1e30f;
        #pragma unroll
        for (int j = 0; j < 8; j++) {
            mx0 = fmaxf(mx0, fmaxf(s[j][0], s[j][1]));
            mx1 = fmaxf(mx1, fmaxf(s[j][2], s[j][3]));
        }
        #pragma unroll
        for (int off = 1; off <= 2; off <<= 1) {
            mx0 = fmaxf(mx0, __shfl_xor_sync(0xffffffffu, mx0, off));
            mx1 = fmaxf(mx1, __shfl_xor_sync(0xffffffffu, mx1, off));
        }
        const float mn0 = fmaxf(m0, mx0), mn1 = fmaxf(m1, mx1);
        const float al0 = __expf(m0 - mn0), al1 = __expf(m1 - mn1);
        m0 = mn0; m1 = mn1;

        unsigned pf[8][2];
        float sum0 = 0.f, sum1 = 0.f;
        #pragma unroll
        for (int j = 0; j < 8; j++) {
            float p0 = __expf(s[j][0] - mn0), p1 = __expf(s[j][1] - mn0);
            float p2 = __expf(s[j][2] - mn1), p3 = __expf(s[j][3] - mn1);
            __half2 h01 = __floats2half2_rn(p0, p1);
            __half2 h23 = __floats2half2_rn(p2, p3);
            pf[j][0] = *(unsigned*)&h01;
            pf[j][1] = *(unsigned*)&h23;
            sum0 += p0 + p1; sum1 += p2 + p3;
        }
        #pragma unroll
        for (int off = 1; off <= 2; off <<= 1) {
            sum0 += __shfl_xor_sync(0xffffffffu, sum0, off);
            sum1 += __shfl_xor_sync(0xffffffffu, sum1, off);
        }
        l0 = l0 * al0 + sum0;
        l1 = l1 * al1 + sum1;
        #pragma unroll
        for (int j = 0; j < 8; j++) {
            o[j][0] *= al0; o[j][1] *= al0;
            o[j][2] *= al1; o[j][3] *= al1;
        }

        const uint32_t vaddr = smem_u32(&KVs[buf][1][0])
            + (uint32_t)(lane & 15) * (ASTR * 2) + ((lane >> 4) << 4);
        #pragma unroll
        for (int ks = 0; ks < 4; ks++) {
            unsigned a[4] = { pf[2 * ks][0], pf[2 * ks][1],
                              pf[2 * ks + 1][0], pf[2 * ks + 1][1] };
            unsigned b[8][2];
            #pragma unroll
            for (int q = 0; q < 4; q++)
                LDSM4T(b[2 * q][0], b[2 * q][1], b[2 * q + 1][0], b[2 * q + 1][1],
                       vaddr + (uint32_t)(ks * 16 * (ASTR * 2)) + q * 32);
            #pragma unroll
            for (int j = 0; j < 8; j++)
                mma_f16(o[j], a, b[j]);
        }
    }

    const float inv0 = 1.0f / l0, inv1 = 1.0f / l1;
    const int row0 = batch * S_ + qbase + w * 16 + gid;
    #pragma unroll
    for (int j = 0; j < 8; j++) {
        int col = hd + j * 8 + tig * 2;
        *(__half2*)(out + (size_t)row0 * D_ + col) =
            __floats2half2_rn(o[j][0] * inv0, o[j][1] * inv0);
        *(__half2*)(out + (size_t)(row0 + 8) * D_ + col) =
            __floats2half2_rn(o[j][2] * inv1, o[j][3] * inv1);
    }
}

// ---------------------------------------------------------------------------
// LayerNorm over D=768 per row; optionally writes an fp16 second copy.
// RED variant: input row = p0 + p1 + bias + res (mlp split-K reduction fused).
// ---------------------------------------------------------------------------
template<bool HCOPY, bool RED>
__global__ __launch_bounds__(256) void ln_kernel(const float* __restrict__ x,
                                                 const float* __restrict__ p1,
                                                 const float* __restrict__ bias,
                                                 const float* __restrict__ res,
                                                 const float* __restrict__ g,
                                                 const float* __restrict__ b,
                                                 float* __restrict__ out,
                                                 __half* __restrict__ outh)
{
    int row = blockIdx.x;
    int tid = threadIdx.x;
    const size_t rb = (size_t)row * D_;
    float v0, v1, v2;
    if (RED) {
        v0 = x[rb + tid]       + p1[rb + tid]       + bias[tid]       + res[rb + tid];
        v1 = x[rb + tid + 256] + p1[rb + tid + 256] + bias[tid + 256] + res[rb + tid + 256];
        v2 = x[rb + tid + 512] + p1[rb + tid + 512] + bias[tid + 512] + res[rb + tid + 512];
    } else {
        v0 = x[rb + tid]; v1 = x[rb + tid + 256]; v2 = x[rb + tid + 512];
    }

    __shared__ float red[8];
    float s = v0 + v1 + v2;
    #pragma unroll
    for (int o = 16; o > 0; o >>= 1) s += __shfl_xor_sync(~0u, s, o);
    if ((tid & 31) == 0) red[tid >> 5] = s;
    __syncthreads();
    float tot = 0.f;
    if (tid < 32) {
        tot = (tid < 8) ? red[tid] : 0.f;
        #pragma unroll
        for (int o = 4; o > 0; o >>= 1) tot += __shfl_xor_sync(~0u, tot, o);
        if (tid == 0) red[0] = tot;
    }
    __syncthreads();
    float mean = red[0] * (1.0f / D_);

    float d0 = v0 - mean, d1 = v1 - mean, d2 = v2 - mean;
    float q = d0 * d0 + d1 * d1 + d2 * d2;
    #pragma unroll
    for (int o = 16; o > 0; o >>= 1) q += __shfl_xor_sync(~0u, q, o);
    __syncthreads();
    if ((tid & 31) == 0) red[tid >> 5] = q;
    __syncthreads();
    if (tid < 32) {
        float t = (tid < 8) ? red[tid] : 0.f;
        #pragma unroll
        for (int o = 4; o > 0; o >>= 1) t += __shfl_xor_sync(~0u, t, o);
        if (tid == 0) red[0] = t;
    }
    __syncthreads();
    float rstd = rsqrtf(red[0] * (1.0f / D_) + 1e-5f);

    float* o = out + rb;
    float y0 = d0 * rstd * g[tid]       + b[tid];
    float y1 = d1 * rstd * g[tid + 256] + b[tid + 256];
    float y2 = d2 * rstd * g[tid + 512] + b[tid + 512];
    o[tid] = y0; o[tid + 256] = y1; o[tid + 512] = y2;
    if (HCOPY) {
        __half* oh = outh + rb;
        oh[tid]       = __float2half_rn(y0);
        oh[tid + 256] = __float2half_rn(y1);
        oh[tid + 512] = __float2half_rn(y2);
    }
}

// ---------------------------------------------------------------------------
// Launch
// ---------------------------------------------------------------------------
extern "C" void kernel_launch(void* const* d_in, const int* in_sizes, int n_in,
                              void* d_out, int out_size)
{
    (void)in_sizes; (void)n_in; (void)out_size;

    const void*  x           = d_in[0];
    const float* we          = (const float*)d_in[1];
    const float* c_attn_w    = (const float*)d_in[2];
    const float* c_attn_b    = (const float*)d_in[3];
    const float* attn_proj_w = (const float*)d_in[4];
    const float* attn_proj_b = (const float*)d_in[5];
    const float* ln1_g       = (const float*)d_in[6];
    const float* ln1_b       = (const float*)d_in[7];
    const float* fc_w        = (const float*)d_in[8];
    const float* fc_b        = (const float*)d_in[9];
    const float* mlp_proj_w  = (const float*)d_in[10];
    const float* mlp_proj_b  = (const float*)d_in[11];
    const float* ln2_g       = (const float*)d_in[12];
    const float* ln2_b       = (const float*)d_in[13];
    float* out = (float*)d_out;

    float *r1, *nbuf, *p2;
    __half *qkv, *attnb, *nr, *hr, *ff;
    __half *cawT, *apwT, *fcwT, *mpwT;
    cudaGetSymbolAddress((void**)&qkv,   g_qkv);
    cudaGetSymbolAddress((void**)&attnb, g_attn);
    cudaGetSymbolAddress((void**)&r1,    g_r1);
    cudaGetSymbolAddress((void**)&nbuf,  g_n);
    cudaGetSymbolAddress((void**)&nr,    g_nr);
    cudaGetSymbolAddress((void**)&hr,    g_hr);
    cudaGetSymbolAddress((void**)&ff,    g_ff);
    cudaGetSymbolAddress((void**)&p2,    g_p2);
    cudaGetSymbolAddress((void**)&cawT,  g_caw_t);
    cudaGetSymbolAddress((void**)&apwT,  g_apw_t);
    cudaGetSymbolAddress((void**)&fcwT,  g_fcw_t);
    cudaGetSymbolAddress((void**)&mpwT,  g_mpw_t);

    // Shape-tuned GEMM variants:
    //   qkv: 512 thr, bias, fp16 out          (deep-wave, N=2304)
    //   fc : 512 thr, bias+gelu, fp16 out     (deep-wave, N=3072)
    //   proj: 256 thr, bias+res, fp32 out     (2-wave, N=768)
    //   mlp : 256 thr, split-K partials       (2-wave, N=768)
    cudaFuncSetAttribute(mma_gemm_kernel<512, true, false, false, true, false>,
                         cudaFuncAttributeMaxDynamicSharedMemorySize, GEMM_SMEM);
    cudaFuncSetAttribute(mma_gemm_kernel<256, true, true, false, false, false>,
                         cudaFuncAttributeMaxDynamicSharedMemorySize, GEMM_SMEM);
    cudaFuncSetAttribute(mma_gemm_kernel<512, true, false, true, true, false>,
                         cudaFuncAttributeMaxDynamicSharedMemorySize, GEMM_SMEM);
    cudaFuncSetAttribute(mma_gemm_kernel<256, false, false, false, false, true>,
                         cudaFuncAttributeMaxDynamicSharedMemorySize, GEMM_SMEM);

    // Single prep launch: embedding + all weight transposes.
    prep_kernel<<<NB_PREP, 256>>>(x, we, out, hr,
                                  c_attn_w, cawT, attn_proj_w, apwT,
                                  fc_w, fcwT, mlp_proj_w, mpwT);

    for (int l = 0; l < L_; l++) {
        const float* h    = out + (size_t)l * BS_ * D_;
        float*       hout = out + (size_t)(l + 1) * BS_ * D_;

        // qkv = h @ caw + cab   (fp16 out)
        mma_gemm_kernel<512, true, false, false, true, false>
            <<<dim3(D3_ / 128, BS_ / 128), 512, GEMM_SMEM>>>(
            hr, cawT + (size_t)l * D3_ * D_, c_attn_b + (size_t)l * D3_,
            nullptr, qkv, BS_, D3_, D_);

        // a = causal_attention(qkv)  (tensor-core, fp16 out)
        attn_kernel<<<dim3(S_ / 64, H_, B_), 128>>>(qkv, attnb);

        // r1 = a @ apw + apb + h
        mma_gemm_kernel<256, true, true, false, false, false>
            <<<dim3(D_ / 128, BS_ / 128), 256, GEMM_SMEM>>>(
            attnb, apwT + (size_t)l * D_ * D_, attn_proj_b + (size_t)l * D_,
            h, r1, BS_, D_, D_);

        // n = LN(r1)  (+ fp16 copy for fc A)
        ln_kernel<true, false><<<BS_, 256>>>(r1, nullptr, nullptr, nullptr,
                                             ln1_g + (size_t)l * D_,
                                             ln1_b + (size_t)l * D_, nbuf, nr);

        // ff = gelu(n @ fw + fb)  (fp16 out)
        mma_gemm_kernel<512, true, false, true, true, false>
            <<<dim3(FF_ / 128, BS_ / 128), 512, GEMM_SMEM>>>(
            nr, fcwT + (size_t)l * FF_ * D_, fc_b + (size_t)l * FF_,
            nullptr, ff, BS_, FF_, D_);

        // mlp partials: p2[z] = ff[:, z-half] @ pw[z-half]
        mma_gemm_kernel<256, false, false, false, false, true>
            <<<dim3(D_ / 128, BS_ / 128, 2), 256, GEMM_SMEM>>>(
            ff, mpwT + (size_t)l * D_ * FF_, nullptr,
            nullptr, p2, BS_, D_, FF_ / 2);

        // out_{l+1} = LN(p0 + p1 + pb + n)  (+ fp16 copy for next qkv A)
        ln_kernel<true, true><<<BS_, 256>>>(p2, p2 + (size_t)BS_ * D_,
                                            mlp_proj_b + (size_t)l * D_, nbuf,
                                            ln2_g + (size_t)l * D_,
                                            ln2_b + (size_t)l * D_, hout, hr);
    }
}

// round 16
// speedup vs baseline: 1.0030x; 1.0030x over previous
#include <cuda_runtime.h>
#include <cuda_fp16.h>
#include <math.h>
#include <stdint.h>

// Problem constants
#define B_     16
#define S_     512
#define D_     768
#define H_     12
#define DH_    64
#define L_     12
#define FF_    3072
#define VOCAB_ 40990
#define BS_    (B_ * S_)     // 8192 rows
#define D3_    (3 * D_)      // 2304

// ---------------------------------------------------------------------------
// Scratch (static device globals: allocation-free, graph-capturable)
// ---------------------------------------------------------------------------
__device__ __half g_qkv[(size_t)BS_ * D3_];   // fp16 qkv (attention input)
__device__ __half g_attn[(size_t)BS_ * D_];   // attention out (fp16, proj A)
__device__ float  g_r1[(size_t)BS_ * D_];
__device__ float  g_n[(size_t)BS_ * D_];
__device__ __half g_nr[(size_t)BS_ * D_];     // fp16 n (fc A)
__device__ __half g_hr[(size_t)BS_ * D_];     // fp16 h (qkv A)
__device__ __half g_ff[(size_t)BS_ * FF_];    // fp16 gelu out (mlp A)
__device__ __half g_p2[2 * (size_t)BS_ * D_]; // mlp split-K partials (fp16)
// Transposed ([N,K]) fp16 weight copies
__device__ __half g_caw_t[(size_t)L_ * D3_ * D_];
__device__ __half g_apw_t[(size_t)L_ * D_ * D_];
__device__ __half g_fcw_t[(size_t)L_ * FF_ * D_];
__device__ __half g_mpw_t[(size_t)L_ * D_ * FF_];

// ---------------------------------------------------------------------------
// Helpers
// ---------------------------------------------------------------------------
__device__ __forceinline__ uint32_t smem_u32(const void* p) {
    uint32_t a;
    asm("{ .reg .u64 t; cvta.to.shared.u64 t, %1; cvt.u32.u64 %0, t; }"
        : "=r"(a) : "l"(p));
    return a;
}
__device__ __forceinline__ void mma_f16(float c[4], const unsigned a[4],
                                        const unsigned b[2]) {
    asm volatile(
        "mma.sync.aligned.m16n8k16.row.col.f32.f16.f16.f32 "
        "{%0,%1,%2,%3},{%4,%5,%6,%7},{%8,%9},{%0,%1,%2,%3};"
        : "+f"(c[0]), "+f"(c[1]), "+f"(c[2]), "+f"(c[3])
        : "r"(a[0]), "r"(a[1]), "r"(a[2]), "r"(a[3]), "r"(b[0]), "r"(b[1]));
}
__device__ __forceinline__ void cp16(unsigned smem_addr, const void* gptr) {
    asm volatile("cp.async.cg.shared.global [%0], [%1], 16;\n"
                 :: "r"(smem_addr), "l"(gptr));
}
#define LDSM4(r0, r1, r2, r3, addr) \
    asm volatile("ldmatrix.sync.aligned.m8n8.x4.shared.b16 {%0,%1,%2,%3}, [%4];" \
        : "=r"(r0), "=r"(r1), "=r"(r2), "=r"(r3) : "r"(addr))
#define LDSM4T(r0, r1, r2, r3, addr) \
    asm volatile("ldmatrix.sync.aligned.m8n8.x4.trans.shared.b16 {%0,%1,%2,%3}, [%4];" \
        : "=r"(r0), "=r"(r1), "=r"(r2), "=r"(r3) : "r"(addr))

// Fast GELU: tanh(i) = 1 - 2/(e^{2i}+1); saturates correctly, no NaN path.
__device__ __forceinline__ float gelu_fast(float v) {
    float i = 0.7978845608028654f * (v + 0.044715f * v * v * v);
    float t = 1.0f - 2.0f / (__expf(2.0f * i) + 1.0f);
    return 0.5f * v * (1.0f + t);
}

// ---------------------------------------------------------------------------
// prep_kernel: one launch covering embedding + all 4 weight transposes.
// ---------------------------------------------------------------------------
#define NB_EMBED 8192
#define NB_CAW   ((D3_ / 32) * (D_ / 32) * L_)   // 20736
#define NB_APW   ((D_ / 32) * (D_ / 32) * L_)    // 6912
#define NB_FCW   ((FF_ / 32) * (D_ / 32) * L_)   // 27648
#define NB_MPW   ((D_ / 32) * (FF_ / 32) * L_)   // 27648
#define NB_PREP  (NB_EMBED + NB_CAW + NB_APW + NB_FCW + NB_MPW)

__device__ __forceinline__ void do_transpose(
    const float* __restrict__ W, __half* __restrict__ Wt,
    int K, int N, int bid, float (*t)[33])
{
    const int nbx = N / 32, nby = K / 32;
    const int per_l = nbx * nby;
    const int l = bid / per_l, rem = bid - l * per_l;
    const int bx = rem % nbx, by = rem / nbx;
    const float* Wl = W + (size_t)l * K * N;
    __half* Wtl = Wt + (size_t)l * K * N;
    const int nb = bx * 32, kb = by * 32;
    const int tid = threadIdx.x;
    const int tx = tid & 31, ty = tid >> 5;
    #pragma unroll
    for (int j = 0; j < 32; j += 8)
        t[ty + j][tx] = Wl[(size_t)(kb + ty + j) * N + nb + tx];
    __syncthreads();
    #pragma unroll
    for (int j = 0; j < 2; j++) {
        int n = (tid >> 4) + j * 16;
        int c = tid & 15;
        __half2 v = __floats2half2_rn(t[2 * c][n], t[2 * c + 1][n]);
        *(__half2*)&Wtl[(size_t)(nb + n) * K + kb + 2 * c] = v;
    }
}

__global__ __launch_bounds__(256) void prep_kernel(
    const void* __restrict__ x, const float* __restrict__ we,
    float* __restrict__ out, __half* __restrict__ outh,
    const float* __restrict__ caw, __half* __restrict__ cawT,
    const float* __restrict__ apw, __half* __restrict__ apwT,
    const float* __restrict__ fcw, __half* __restrict__ fcwT,
    const float* __restrict__ mpw, __half* __restrict__ mpwT)
{
    __shared__ float t[32][33];
    __shared__ int is64;
    int b = blockIdx.x;

    if (b < NB_EMBED) {
        if (threadIdx.x == 0) {
            const unsigned long long* p = (const unsigned long long*)x;
            int ok = 1;
            #pragma unroll 1
            for (int i = 0; i < 64; i++)
                if (p[i] >= (unsigned long long)VOCAB_) { ok = 0; break; }
            is64 = ok;
        }
        __syncthreads();
        long long i0, i1;
        if (is64) {
            const long long* p = (const long long*)x;
            i0 = p[2 * b]; i1 = p[2 * b + 1];
        } else {
            const int* p = (const int*)x;
            i0 = p[2 * b]; i1 = p[2 * b + 1];
        }
        const float* w0 = we + (size_t)i0 * D_;
        const float* w1 = we + (size_t)i1 * D_;
        float* o = out + (size_t)b * D_;
        __half* oh = outh + (size_t)b * D_;
        for (int c = threadIdx.x; c < D_; c += 256) {
            float v = w0[c] + w1[c];
            o[c] = v;
            oh[c] = __float2half_rn(v);
        }
        return;
    }
    b -= NB_EMBED;
    if (b < NB_CAW) { do_transpose(caw, cawT, D_, D3_, b, t); return; }
    b -= NB_CAW;
    if (b < NB_APW) { do_transpose(apw, apwT, D_, D_, b, t); return; }
    b -= NB_APW;
    if (b < NB_FCW) { do_transpose(fcw, fcwT, D_, FF_, b, t); return; }
    b -= NB_FCW;
    do_transpose(mpw, mpwT, FF_, D_, b, t);
}

// ---------------------------------------------------------------------------
// FP16 MMA GEMM: 512 threads (16 warps), warp tile 32x32, CTA tile
// 128x128x64, 3-stage cp.async pipeline, ldmatrix fragments, fp32
// accumulate/epilogue. (All-512 config = round-14 measured best.)
// C[M,N] = A[M,K] @ Bt[N,K]^T (+bias)(+res)(gelu).
// SPLITK: blockIdx.z selects a K-half (caller passes K = K_orig/2; operand
// row stride is 2K); partial written to C + z*M*N (fp16 when HALFOUT).
// ---------------------------------------------------------------------------
#define RSH     72                       // row stride in halves
#define OPB     (128 * RSH * 2)          // bytes per operand per stage (18432)
#define STGB    (2 * OPB)                // bytes per stage (36864)
#define NSTG    3
#define GEMM_SMEM (NSTG * STGB)          // 110592 bytes
#define GTHREADS 512

template<bool BIAS, bool RES, bool DOGELU, bool HALFOUT, bool SPLITK>
__global__ __launch_bounds__(GTHREADS, 2) void mma_gemm_kernel(
    const __half* __restrict__ A, const __half* __restrict__ Bt,
    const float* __restrict__ bias, const float* __restrict__ res,
    void* __restrict__ Cv, int M, int N, int K)
{
    extern __shared__ char smem[];
    const int lda = SPLITK ? (K << 1) : K;   // operand row stride
    if (SPLITK) {
        const int kz = blockIdx.z;
        A  += (size_t)kz * K;
        Bt += (size_t)kz * K;
        if (HALFOUT) Cv = (void*)((__half*)Cv + (size_t)kz * M * N);
        else         Cv = (void*)((float*)Cv + (size_t)kz * M * N);
    }

    const int tid  = threadIdx.x;
    const int lane = tid & 31;
    const int wid  = tid >> 5;    // 0..15
    const int gid  = lane >> 2;
    const int tig  = lane & 3;
    const int warp_m = wid >> 2;  // 0..3 -> 32-row slab
    const int warp_n = wid & 3;   // 0..3 -> 32-col slab
    const int bm = blockIdx.y * 128, bn = blockIdx.x * 128;

    const __half* Arow = A + (size_t)bm * lda;
    const __half* Brow = Bt + (size_t)bn * lda;

    const int frow = tid >> 3;        // 0..63 (+h*64)
    const int fcol = (tid & 7) * 8;   // halves

    auto load_stage = [&](int s, int ic) {
        char* As = smem + s * STGB;
        char* Bs = As + OPB;
        const int k0 = ic << 6;
        #pragma unroll
        for (int h = 0; h < 2; h++) {
            int r = h * 64 + frow;
            cp16((unsigned)__cvta_generic_to_shared(As + (r * RSH + fcol) * 2),
                 Arow + (size_t)r * lda + k0 + fcol);
        }
        #pragma unroll
        for (int h = 0; h < 2; h++) {
            int r = h * 64 + frow;
            cp16((unsigned)__cvta_generic_to_shared(Bs + (r * RSH + fcol) * 2),
                 Brow + (size_t)r * lda + k0 + fcol);
        }
        asm volatile("cp.async.commit_group;" ::: "memory");
    };

    float acc[2][4][4];
    #pragma unroll
    for (int i = 0; i < 2; i++)
        #pragma unroll
        for (int j = 0; j < 4; j++)
            #pragma unroll
            for (int c = 0; c < 4; c++) acc[i][j][c] = 0.f;

    const uint32_t sbase = smem_u32(smem);
    const uint32_t aoff =
        (uint32_t)(warp_m * 32 + (lane & 15)) * (RSH * 2) + ((lane >> 4) << 4);
    const uint32_t boff =
        (uint32_t)(warp_n * 32 + (lane & 7) + ((lane >> 4) << 3)) * (RSH * 2)
        + (((lane >> 3) & 1) << 4);

    const int NK = K >> 6;
    load_stage(0, 0);
    load_stage(1, 1);

    for (int it = 0; it < NK; it++) {
        if (it + 1 < NK)
            asm volatile("cp.async.wait_group 1;" ::: "memory");
        else
            asm volatile("cp.async.wait_group 0;" ::: "memory");
        __syncthreads();
        if (it + 2 < NK) load_stage((it + 2) % NSTG, it + 2);

        const uint32_t sA = sbase + (uint32_t)((it % NSTG) * STGB);
        const uint32_t sB = sA + OPB;

        #pragma unroll
        for (int ks = 0; ks < 4; ks++) {
            const uint32_t kb = ks * 32;
            unsigned a[2][4];
            LDSM4(a[0][0], a[0][1], a[0][2], a[0][3], sA + aoff + kb);
            LDSM4(a[1][0], a[1][1], a[1][2], a[1][3],
                  sA + aoff + 16u * (RSH * 2) + kb);
            unsigned b[4][2];
            #pragma unroll
            for (int q = 0; q < 2; q++)
                LDSM4(b[2 * q][0], b[2 * q][1], b[2 * q + 1][0], b[2 * q + 1][1],
                      sB + boff + (uint32_t)(q * 16 * (RSH * 2)) + kb);
            #pragma unroll
            for (int im = 0; im < 2; im++)
                #pragma unroll
                for (int j = 0; j < 4; j++)
                    mma_f16(acc[im][j], a[im], b[j]);
        }
    }

    float* Cf = (float*)Cv;
    __half* Ch = (__half*)Cv;
    #pragma unroll
    for (int im = 0; im < 2; im++) {
        #pragma unroll
        for (int j = 0; j < 4; j++) {
            int r = bm + warp_m * 32 + im * 16 + gid;
            int c = bn + warp_n * 32 + j * 8 + tig * 2;
            #pragma unroll
            for (int half_ = 0; half_ < 2; half_++) {
                int rr = r + half_ * 8;
                float v0 = acc[im][j][half_ * 2 + 0];
                float v1 = acc[im][j][half_ * 2 + 1];
                if (BIAS) { v0 += bias[c]; v1 += bias[c + 1]; }
                if (RES) {
                    const float* rp = res + (size_t)rr * N + c;
                    v0 += rp[0]; v1 += rp[1];
                }
                if (DOGELU) {
                    v0 = gelu_fast(v0);
                    v1 = gelu_fast(v1);
                }
                if (HALFOUT) {
                    *(__half2*)(Ch + (size_t)rr * N + c) =
                        __floats2half2_rn(v0, v1);
                } else {
                    *(float2*)(Cf + (size_t)rr * N + c) = make_float2(v0, v1);
                }
            }
        }
    }
}

// ---------------------------------------------------------------------------
// Tensor-core fp16 flash attention (64-q blocks, 4 warps, 4 CTAs/SM,
// heavy q-tiles first).
// ---------------------------------------------------------------------------
#define ASTR 72   // smem row stride in halves (144B)

__global__ __launch_bounds__(128, 4) void attn_kernel(
    const __half* __restrict__ qkv, __half* __restrict__ out)
{
    __shared__ __half Qs[64 * ASTR];          // 9216 B
    __shared__ __half KVs[2][2][64 * ASTR];   // 36864 B  [buf][K=0/V=1]

    const int tid = threadIdx.x, lane = tid & 31, w = tid >> 5;
    const int gid = lane >> 2, tig = lane & 3;
    const int qt = (int)gridDim.x - 1 - (int)blockIdx.x;   // heavy tiles first
    const int head = blockIdx.y, batch = blockIdx.z;
    const int qbase = qt * 64;
    const __half* base = qkv + (size_t)batch * S_ * D3_;
    const int hd = head * DH_;

    #pragma unroll
    for (int i = 0; i < 4; i++) {
        int id = tid + i * 128;
        int r = id >> 3, c = (id & 7) * 8;
        cp16(smem_u32(Qs + r * ASTR + c),
             base + (size_t)(qbase + r) * D3_ + hd + c);
    }

    auto load_kv = [&](int buf, int kt) {
        #pragma unroll
        for (int i = 0; i < 4; i++) {
            int id = tid + i * 128;
            int r = id >> 3, c = (id & 7) * 8;
            const __half* krow = base + (size_t)(kt * 64 + r) * D3_;
            cp16(smem_u32(&KVs[buf][0][r * ASTR + c]), krow + D_ + hd + c);
            cp16(smem_u32(&KVs[buf][1][r * ASTR + c]), krow + 2 * D_ + hd + c);
        }
        asm volatile("cp.async.commit_group;" ::: "memory");
    };

    const int ntk = qt + 1;
    load_kv(0, 0);
    asm volatile("cp.async.wait_group 0;" ::: "memory");
    __syncthreads();

    unsigned qf[4][4];
    {
        const uint32_t qaddr = smem_u32(Qs)
            + (uint32_t)(w * 16 + (lane & 15)) * (ASTR * 2) + ((lane >> 4) << 4);
        #pragma unroll
        for (int ks = 0; ks < 4; ks++)
            LDSM4(qf[ks][0], qf[ks][1], qf[ks][2], qf[ks][3], qaddr + 32 * ks);
        const __half2 sc = __float2half2_rn(0.125f);
        #pragma unroll
        for (int ks = 0; ks < 4; ks++)
            #pragma unroll
            for (int i = 0; i < 4; i++) {
                __half2 h = *(__half2*)&qf[ks][i];
                h = __hmul2(h, sc);
                qf[ks][i] = *(unsigned*)&h;
            }
    }

    float m0 = -1e30f, m1 = -1e30f, l0 = 0.f, l1 = 0.f;
    float o[8][4];
    #pragma unroll
    for (int j = 0; j < 8; j++)
        #pragma unroll
        for (int c = 0; c < 4; c++) o[j][c] = 0.f;

    for (int kt = 0; kt < ntk; kt++) {
        const int buf = kt & 1;
        if (kt > 0) {
            asm volatile("cp.async.wait_group 0;" ::: "memory");
            __syncthreads();
        }
        if (kt + 1 < ntk) load_kv(buf ^ 1, kt + 1);

        float s[8][4];
        #pragma unroll
        for (int j = 0; j < 8; j++)
            #pragma unroll
            for (int c = 0; c < 4; c++) s[j][c] = 0.f;

        const uint32_t kaddr = smem_u32(&KVs[buf][0][0])
            + (uint32_t)((lane & 7) + ((lane >> 4) << 3)) * (ASTR * 2)
            + (((lane >> 3) & 1) << 4);
        #pragma unroll
        for (int ks = 0; ks < 4; ks++) {
            unsigned b[8][2];
            #pragma unroll
            for (int q = 0; q < 4; q++)
                LDSM4(b[2 * q][0], b[2 * q][1], b[2 * q + 1][0], b[2 * q + 1][1],
                      kaddr + (uint32_t)(q * 16 * (ASTR * 2)) + 32 * ks);
            #pragma unroll
            for (int j = 0; j < 8; j++)
                mma_f16(s[j], qf[ks], b[j]);
        }

        if (kt == qt) {
            const int rA = w * 16 + gid;
            #pragma unroll
            for (int j = 0; j < 8; j++) {
                int c0 = j * 8 + tig * 2, c1 = c0 + 1;
                if (c0 > rA)     s[j][0] = -1e30f;
                if (c1 > rA)     s[j][1] = -1e30f;
                if (c0 > rA + 8) s[j][2] = -1e30f;
                if (c1 > rA + 8) s[j][3] = -1e30f;
            }
        }

        float mx0 = -1e30f, mx1 = -1e30f;
        #pragma unroll
        for (int j = 0; j < 8; j++) {
            mx0 = fmaxf(mx0, fmaxf(s[j][0], s[j][1]));
            mx1 = fmaxf(mx1, fmaxf(s[j][2], s[j][3]));
        }
        #pragma unroll
        for (int off = 1; off <= 2; off <<= 1) {
            mx0 = fmaxf(mx0, __shfl_xor_sync(0xffffffffu, mx0, off));
            mx1 = fmaxf(mx1, __shfl_xor_sync(0xffffffffu, mx1, off));
        }
        const float mn0 = fmaxf(m0, mx0), mn1 = fmaxf(m1, mx1);
        const float al0 = __expf(m0 - mn0), al1 = __expf(m1 - mn1);
        m0 = mn0; m1 = mn1;

        unsigned pf[8][2];
        float sum0 = 0.f, sum1 = 0.f;
        #pragma unroll
        for (int j = 0; j < 8; j++) {
            float p0 = __expf(s[j][0] - mn0), p1 = __expf(s[j][1] - mn0);
            float p2 = __expf(s[j][2] - mn1), p3 = __expf(s[j][3] - mn1);
            __half2 h01 = __floats2half2_rn(p0, p1);
            __half2 h23 = __floats2half2_rn(p2, p3);
            pf[j][0] = *(unsigned*)&h01;
            pf[j][1] = *(unsigned*)&h23;
            sum0 += p0 + p1; sum1 += p2 + p3;
        }
        #pragma unroll
        for (int off = 1; off <= 2; off <<= 1) {
            sum0 += __shfl_xor_sync(0xffffffffu, sum0, off);
            sum1 += __shfl_xor_sync(0xffffffffu, sum1, off);
        }
        l0 = l0 * al0 + sum0;
        l1 = l1 * al1 + sum1;
        #pragma unroll
        for (int j = 0; j < 8; j++) {
            o[j][0] *= al0; o[j][1] *= al0;
            o[j][2] *= al1; o[j][3] *= al1;
        }

        const uint32_t vaddr = smem_u32(&KVs[buf][1][0])
            + (uint32_t)(lane & 15) * (ASTR * 2) + ((lane >> 4) << 4);
        #pragma unroll
        for (int ks = 0; ks < 4; ks++) {
            unsigned a[4] = { pf[2 * ks][0], pf[2 * ks][1],
                              pf[2 * ks + 1][0], pf[2 * ks + 1][1] };
            unsigned b[8][2];
            #pragma unroll
            for (int q = 0; q < 4; q++)
                LDSM4T(b[2 * q][0], b[2 * q][1], b[2 * q + 1][0], b[2 * q + 1][1],
                       vaddr + (uint32_t)(ks * 16 * (ASTR * 2)) + q * 32);
            #pragma unroll
            for (int j = 0; j < 8; j++)
                mma_f16(o[j], a, b[j]);
        }
    }

    const float inv0 = 1.0f / l0, inv1 = 1.0f / l1;
    const int row0 = batch * S_ + qbase + w * 16 + gid;
    #pragma unroll
    for (int j = 0; j < 8; j++) {
        int col = hd + j * 8 + tig * 2;
        *(__half2*)(out + (size_t)row0 * D_ + col) =
            __floats2half2_rn(o[j][0] * inv0, o[j][1] * inv0);
        *(__half2*)(out + (size_t)(row0 + 8) * D_ + col) =
            __floats2half2_rn(o[j][2] * inv1, o[j][3] * inv1);
    }
}

// ---------------------------------------------------------------------------
// LayerNorm over D=768 per row; optionally writes an fp16 second copy.
// RED variant: input row = half(p0) + half(p1) + bias + res
// (mlp split-K reduction fused; partials are fp16 to halve read traffic).
// ---------------------------------------------------------------------------
template<bool HCOPY, bool RED>
__global__ __launch_bounds__(256) void ln_kernel(const float* __restrict__ x,
                                                 const __half* __restrict__ hp0,
                                                 const __half* __restrict__ hp1,
                                                 const float* __restrict__ bias,
                                                 const float* __restrict__ res,
                                                 const float* __restrict__ g,
                                                 const float* __restrict__ b,
                                                 float* __restrict__ out,
                                                 __half* __restrict__ outh)
{
    int row = blockIdx.x;
    int tid = threadIdx.x;
    const size_t rb = (size_t)row * D_;
    float v0, v1, v2;
    if (RED) {
        v0 = __half2float(hp0[rb + tid])       + __half2float(hp1[rb + tid])
           + bias[tid]       + res[rb + tid];
        v1 = __half2float(hp0[rb + tid + 256]) + __half2float(hp1[rb + tid + 256])
           + bias[tid + 256] + res[rb + tid + 256];
        v2 = __half2float(hp0[rb + tid + 512]) + __half2float(hp1[rb + tid + 512])
           + bias[tid + 512] + res[rb + tid + 512];
    } else {
        v0 = x[rb + tid]; v1 = x[rb + tid + 256]; v2 = x[rb + tid + 512];
    }

    __shared__ float red[8];
    float s = v0 + v1 + v2;
    #pragma unroll
    for (int o = 16; o > 0; o >>= 1) s += __shfl_xor_sync(~0u, s, o);
    if ((tid & 31) == 0) red[tid >> 5] = s;
    __syncthreads();
    float tot = 0.f;
    if (tid < 32) {
        tot = (tid < 8) ? red[tid] : 0.f;
        #pragma unroll
        for (int o = 4; o > 0; o >>= 1) tot += __shfl_xor_sync(~0u, tot, o);
        if (tid == 0) red[0] = tot;
    }
    __syncthreads();
    float mean = red[0] * (1.0f / D_);

    float d0 = v0 - mean, d1 = v1 - mean, d2 = v2 - mean;
    float q = d0 * d0 + d1 * d1 + d2 * d2;
    #pragma unroll
    for (int o = 16; o > 0; o >>= 1) q += __shfl_xor_sync(~0u, q, o);
    __syncthreads();
    if ((tid & 31) == 0) red[tid >> 5] = q;
    __syncthreads();
    if (tid < 32) {
        float t = (tid < 8) ? red[tid] : 0.f;
        #pragma unroll
        for (int o = 4; o > 0; o >>= 1) t += __shfl_xor_sync(~0u, t, o);
        if (tid == 0) red[0] = t;
    }
    __syncthreads();
    float rstd = rsqrtf(red[0] * (1.0f / D_) + 1e-5f);

    float* o = out + rb;
    float y0 = d0 * rstd * g[tid]       + b[tid];
    float y1 = d1 * rstd * g[tid + 256] + b[tid + 256];
    float y2 = d2 * rstd * g[tid + 512] + b[tid + 512];
    o[tid] = y0; o[tid + 256] = y1; o[tid + 512] = y2;
    if (HCOPY) {
        __half* oh = outh + rb;
        oh[tid]       = __float2half_rn(y0);
        oh[tid + 256] = __float2half_rn(y1);
        oh[tid + 512] = __float2half_rn(y2);
    }
}

// ---------------------------------------------------------------------------
// Launch
// ---------------------------------------------------------------------------
extern "C" void kernel_launch(void* const* d_in, const int* in_sizes, int n_in,
                              void* d_out, int out_size)
{
    (void)in_sizes; (void)n_in; (void)out_size;

    const void*  x           = d_in[0];
    const float* we          = (const float*)d_in[1];
    const float* c_attn_w    = (const float*)d_in[2];
    const float* c_attn_b    = (const float*)d_in[3];
    const float* attn_proj_w = (const float*)d_in[4];
    const float* attn_proj_b = (const float*)d_in[5];
    const float* ln1_g       = (const float*)d_in[6];
    const float* ln1_b       = (const float*)d_in[7];
    const float* fc_w        = (const float*)d_in[8];
    const float* fc_b        = (const float*)d_in[9];
    const float* mlp_proj_w  = (const float*)d_in[10];
    const float* mlp_proj_b  = (const float*)d_in[11];
    const float* ln2_g       = (const float*)d_in[12];
    const float* ln2_b       = (const float*)d_in[13];
    float* out = (float*)d_out;

    float *r1, *nbuf;
    __half *qkv, *attnb, *nr, *hr, *ff, *p2h;
    __half *cawT, *apwT, *fcwT, *mpwT;
    cudaGetSymbolAddress((void**)&qkv,   g_qkv);
    cudaGetSymbolAddress((void**)&attnb, g_attn);
    cudaGetSymbolAddress((void**)&r1,    g_r1);
    cudaGetSymbolAddress((void**)&nbuf,  g_n);
    cudaGetSymbolAddress((void**)&nr,    g_nr);
    cudaGetSymbolAddress((void**)&hr,    g_hr);
    cudaGetSymbolAddress((void**)&ff,    g_ff);
    cudaGetSymbolAddress((void**)&p2h,   g_p2);
    cudaGetSymbolAddress((void**)&cawT,  g_caw_t);
    cudaGetSymbolAddress((void**)&apwT,  g_apw_t);
    cudaGetSymbolAddress((void**)&fcwT,  g_fcw_t);
    cudaGetSymbolAddress((void**)&mpwT,  g_mpw_t);

    cudaFuncSetAttribute(mma_gemm_kernel<true, false, false, true, false>,
                         cudaFuncAttributeMaxDynamicSharedMemorySize, GEMM_SMEM);
    cudaFuncSetAttribute(mma_gemm_kernel<true, true, false, false, false>,
                         cudaFuncAttributeMaxDynamicSharedMemorySize, GEMM_SMEM);
    cudaFuncSetAttribute(mma_gemm_kernel<true, false, true, true, false>,
                         cudaFuncAttributeMaxDynamicSharedMemorySize, GEMM_SMEM);
    cudaFuncSetAttribute(mma_gemm_kernel<false, false, false, true, true>,
                         cudaFuncAttributeMaxDynamicSharedMemorySize, GEMM_SMEM);

    // Single prep launch: embedding + all weight transposes.
    prep_kernel<<<NB_PREP, 256>>>(x, we, out, hr,
                                  c_attn_w, cawT, attn_proj_w, apwT,
                                  fc_w, fcwT, mlp_proj_w, mpwT);

    for (int l = 0; l < L_; l++) {
        const float* h    = out + (size_t)l * BS_ * D_;
        float*       hout = out + (size_t)(l + 1) * BS_ * D_;

        // qkv = h @ caw + cab   (fp16 out)
        mma_gemm_kernel<true, false, false, true, false>
            <<<dim3(D3_ / 128, BS_ / 128), GTHREADS, GEMM_SMEM>>>(
            hr, cawT + (size_t)l * D3_ * D_, c_attn_b + (size_t)l * D3_,
            nullptr, qkv, BS_, D3_, D_);

        // a = causal_attention(qkv)  (tensor-core, fp16 out)
        attn_kernel<<<dim3(S_ / 64, H_, B_), 128>>>(qkv, attnb);

        // r1 = a @ apw + apb + h
        mma_gemm_kernel<true, true, false, false, false>
            <<<dim3(D_ / 128, BS_ / 128), GTHREADS, GEMM_SMEM>>>(
            attnb, apwT + (size_t)l * D_ * D_, attn_proj_b + (size_t)l * D_,
            h, r1, BS_, D_, D_);

        // n = LN(r1)  (+ fp16 copy for fc A)
        ln_kernel<true, false><<<BS_, 256>>>(r1, nullptr, nullptr, nullptr,
                                             nullptr,
                                             ln1_g + (size_t)l * D_,
                                             ln1_b + (size_t)l * D_, nbuf, nr);

        // ff = gelu(n @ fw + fb)  (fp16 out)
        mma_gemm_kernel<true, false, true, true, false>
            <<<dim3(FF_ / 128, BS_ / 128), GTHREADS, GEMM_SMEM>>>(
            nr, fcwT + (size_t)l * FF_ * D_, fc_b + (size_t)l * FF_,
            nullptr, ff, BS_, FF_, D_);

        // mlp partials (fp16): p2[z] = ff[:, z-half] @ pw[z-half]
        mma_gemm_kernel<false, false, false, true, true>
            <<<dim3(D_ / 128, BS_ / 128, 2), GTHREADS, GEMM_SMEM>>>(
            ff, mpwT + (size_t)l * D_ * FF_, nullptr,
            nullptr, p2h, BS_, D_, FF_ / 2);

        // out_{l+1} = LN(p0 + p1 + pb + n)  (+ fp16 copy for next qkv A)
        ln_kernel<true, true><<<BS_, 256>>>(nullptr, p2h, p2h + (size_t)BS_ * D_,
                                            mlp_proj_b + (size_t)l * D_, nbuf,
                                            ln2_g + (size_t)l * D_,
                                            ln2_b + (size_t)l * D_, hout, hr);
    }
}

// round 17
// speedup vs baseline: 1.0266x; 1.0236x over previous
#include <cuda_runtime.h>
#include <cuda_fp16.h>
#include <math.h>
#include <stdint.h>

// Problem constants
#define B_     16
#define S_     512
#define D_     768
#define H_     12
#define DH_    64
#define L_     12
#define FF_    3072
#define VOCAB_ 40990
#define BS_    (B_ * S_)     // 8192 rows
#define D3_    (3 * D_)      // 2304

// ---------------------------------------------------------------------------
// Scratch (static device globals: allocation-free, graph-capturable)
// ---------------------------------------------------------------------------
__device__ __half g_qkv[(size_t)BS_ * D3_];   // fp16 qkv (attention input)
__device__ __half g_attn[(size_t)BS_ * D_];   // attention out (fp16, proj A)
__device__ float  g_n[(size_t)BS_ * D_];      // fp32 n (ln2 residual)
__device__ __half g_nr[(size_t)BS_ * D_];     // fp16 n (fc A)
__device__ __half g_hr[(size_t)BS_ * D_];     // fp16 h (qkv A)
__device__ __half g_ff[(size_t)BS_ * FF_];    // fp16 gelu out (mlp A)
__device__ __half g_p2[2 * (size_t)BS_ * D_]; // split-K partials (fp16; proj & mlp)
// Transposed ([N,K]) fp16 weight copies
__device__ __half g_caw_t[(size_t)L_ * D3_ * D_];
__device__ __half g_apw_t[(size_t)L_ * D_ * D_];
__device__ __half g_fcw_t[(size_t)L_ * FF_ * D_];
__device__ __half g_mpw_t[(size_t)L_ * D_ * FF_];

// ---------------------------------------------------------------------------
// Helpers
// ---------------------------------------------------------------------------
__device__ __forceinline__ uint32_t smem_u32(const void* p) {
    uint32_t a;
    asm("{ .reg .u64 t; cvta.to.shared.u64 t, %1; cvt.u32.u64 %0, t; }"
        : "=r"(a) : "l"(p));
    return a;
}
__device__ __forceinline__ void mma_f16(float c[4], const unsigned a[4],
                                        const unsigned b[2]) {
    asm volatile(
        "mma.sync.aligned.m16n8k16.row.col.f32.f16.f16.f32 "
        "{%0,%1,%2,%3},{%4,%5,%6,%7},{%8,%9},{%0,%1,%2,%3};"
        : "+f"(c[0]), "+f"(c[1]), "+f"(c[2]), "+f"(c[3])
        : "r"(a[0]), "r"(a[1]), "r"(a[2]), "r"(a[3]), "r"(b[0]), "r"(b[1]));
}
__device__ __forceinline__ void cp16(unsigned smem_addr, const void* gptr) {
    asm volatile("cp.async.cg.shared.global [%0], [%1], 16;\n"
                 :: "r"(smem_addr), "l"(gptr));
}
#define LDSM4(r0, r1, r2, r3, addr) \
    asm volatile("ldmatrix.sync.aligned.m8n8.x4.shared.b16 {%0,%1,%2,%3}, [%4];" \
        : "=r"(r0), "=r"(r1), "=r"(r2), "=r"(r3) : "r"(addr))
#define LDSM4T(r0, r1, r2, r3, addr) \
    asm volatile("ldmatrix.sync.aligned.m8n8.x4.trans.shared.b16 {%0,%1,%2,%3}, [%4];" \
        : "=r"(r0), "=r"(r1), "=r"(r2), "=r"(r3) : "r"(addr))

// Fast GELU: tanh(i) = 1 - 2/(e^{2i}+1); saturates correctly, no NaN path.
__device__ __forceinline__ float gelu_fast(float v) {
    float i = 0.7978845608028654f * (v + 0.044715f * v * v * v);
    float t = 1.0f - 2.0f / (__expf(2.0f * i) + 1.0f);
    return 0.5f * v * (1.0f + t);
}

// ---------------------------------------------------------------------------
// prep_kernel: one launch covering embedding + all 4 weight transposes.
// ---------------------------------------------------------------------------
#define NB_EMBED 8192
#define NB_CAW   ((D3_ / 32) * (D_ / 32) * L_)   // 20736
#define NB_APW   ((D_ / 32) * (D_ / 32) * L_)    // 6912
#define NB_FCW   ((FF_ / 32) * (D_ / 32) * L_)   // 27648
#define NB_MPW   ((D_ / 32) * (FF_ / 32) * L_)   // 27648
#define NB_PREP  (NB_EMBED + NB_CAW + NB_APW + NB_FCW + NB_MPW)

__device__ __forceinline__ void do_transpose(
    const float* __restrict__ W, __half* __restrict__ Wt,
    int K, int N, int bid, float (*t)[33])
{
    const int nbx = N / 32, nby = K / 32;
    const int per_l = nbx * nby;
    const int l = bid / per_l, rem = bid - l * per_l;
    const int bx = rem % nbx, by = rem / nbx;
    const float* Wl = W + (size_t)l * K * N;
    __half* Wtl = Wt + (size_t)l * K * N;
    const int nb = bx * 32, kb = by * 32;
    const int tid = threadIdx.x;
    const int tx = tid & 31, ty = tid >> 5;
    #pragma unroll
    for (int j = 0; j < 32; j += 8)
        t[ty + j][tx] = Wl[(size_t)(kb + ty + j) * N + nb + tx];
    __syncthreads();
    #pragma unroll
    for (int j = 0; j < 2; j++) {
        int n = (tid >> 4) + j * 16;
        int c = tid & 15;
        __half2 v = __floats2half2_rn(t[2 * c][n], t[2 * c + 1][n]);
        *(__half2*)&Wtl[(size_t)(nb + n) * K + kb + 2 * c] = v;
    }
}

__global__ __launch_bounds__(256) void prep_kernel(
    const void* __restrict__ x, const float* __restrict__ we,
    float* __restrict__ out, __half* __restrict__ outh,
    const float* __restrict__ caw, __half* __restrict__ cawT,
    const float* __restrict__ apw, __half* __restrict__ apwT,
    const float* __restrict__ fcw, __half* __restrict__ fcwT,
    const float* __restrict__ mpw, __half* __restrict__ mpwT)
{
    __shared__ float t[32][33];
    __shared__ int is64;
    int b = blockIdx.x;

    if (b < NB_EMBED) {
        if (threadIdx.x == 0) {
            const unsigned long long* p = (const unsigned long long*)x;
            int ok = 1;
            #pragma unroll 1
            for (int i = 0; i < 64; i++)
                if (p[i] >= (unsigned long long)VOCAB_) { ok = 0; break; }
            is64 = ok;
        }
        __syncthreads();
        long long i0, i1;
        if (is64) {
            const long long* p = (const long long*)x;
            i0 = p[2 * b]; i1 = p[2 * b + 1];
        } else {
            const int* p = (const int*)x;
            i0 = p[2 * b]; i1 = p[2 * b + 1];
        }
        const float* w0 = we + (size_t)i0 * D_;
        const float* w1 = we + (size_t)i1 * D_;
        float* o = out + (size_t)b * D_;
        __half* oh = outh + (size_t)b * D_;
        for (int c = threadIdx.x; c < D_; c += 256) {
            float v = w0[c] + w1[c];
            o[c] = v;
            oh[c] = __float2half_rn(v);
        }
        return;
    }
    b -= NB_EMBED;
    if (b < NB_CAW) { do_transpose(caw, cawT, D_, D3_, b, t); return; }
    b -= NB_CAW;
    if (b < NB_APW) { do_transpose(apw, apwT, D_, D_, b, t); return; }
    b -= NB_APW;
    if (b < NB_FCW) { do_transpose(fcw, fcwT, D_, FF_, b, t); return; }
    b -= NB_FCW;
    do_transpose(mpw, mpwT, FF_, D_, b, t);
}

// ---------------------------------------------------------------------------
// FP16 MMA GEMM: 512 threads (16 warps), warp tile 32x32, CTA tile
// 128x128x64, 3-stage cp.async pipeline, ldmatrix fragments, fp32
// accumulate/epilogue. (All-512 config = measured best.)
// C[M,N] = A[M,K] @ Bt[N,K]^T (+bias)(+gelu).
// SPLITK: blockIdx.z selects a K-half (caller passes K = K_orig/2; operand
// row stride is 2K); fp16 partial written to C + z*M*N, no bias.
// ---------------------------------------------------------------------------
#define RSH     72                       // row stride in halves
#define OPB     (128 * RSH * 2)          // bytes per operand per stage (18432)
#define STGB    (2 * OPB)                // bytes per stage (36864)
#define NSTG    3
#define GEMM_SMEM (NSTG * STGB)          // 110592 bytes
#define GTHREADS 512

template<bool BIAS, bool DOGELU, bool HALFOUT, bool SPLITK>
__global__ __launch_bounds__(GTHREADS, 2) void mma_gemm_kernel(
    const __half* __restrict__ A, const __half* __restrict__ Bt,
    const float* __restrict__ bias,
    void* __restrict__ Cv, int M, int N, int K)
{
    extern __shared__ char smem[];
    const int lda = SPLITK ? (K << 1) : K;   // operand row stride
    if (SPLITK) {
        const int kz = blockIdx.z;
        A  += (size_t)kz * K;
        Bt += (size_t)kz * K;
        if (HALFOUT) Cv = (void*)((__half*)Cv + (size_t)kz * M * N);
        else         Cv = (void*)((float*)Cv + (size_t)kz * M * N);
    }

    const int tid  = threadIdx.x;
    const int lane = tid & 31;
    const int wid  = tid >> 5;    // 0..15
    const int gid  = lane >> 2;
    const int tig  = lane & 3;
    const int warp_m = wid >> 2;  // 0..3 -> 32-row slab
    const int warp_n = wid & 3;   // 0..3 -> 32-col slab
    const int bm = blockIdx.y * 128, bn = blockIdx.x * 128;

    const __half* Arow = A + (size_t)bm * lda;
    const __half* Brow = Bt + (size_t)bn * lda;

    const int frow = tid >> 3;        // 0..63 (+h*64)
    const int fcol = (tid & 7) * 8;   // halves

    auto load_stage = [&](int s, int ic) {
        char* As = smem + s * STGB;
        char* Bs = As + OPB;
        const int k0 = ic << 6;
        #pragma unroll
        for (int h = 0; h < 2; h++) {
            int r = h * 64 + frow;
            cp16((unsigned)__cvta_generic_to_shared(As + (r * RSH + fcol) * 2),
                 Arow + (size_t)r * lda + k0 + fcol);
        }
        #pragma unroll
        for (int h = 0; h < 2; h++) {
            int r = h * 64 + frow;
            cp16((unsigned)__cvta_generic_to_shared(Bs + (r * RSH + fcol) * 2),
                 Brow + (size_t)r * lda + k0 + fcol);
        }
        asm volatile("cp.async.commit_group;" ::: "memory");
    };

    float acc[2][4][4];
    #pragma unroll
    for (int i = 0; i < 2; i++)
        #pragma unroll
        for (int j = 0; j < 4; j++)
            #pragma unroll
            for (int c = 0; c < 4; c++) acc[i][j][c] = 0.f;

    const uint32_t sbase = smem_u32(smem);
    const uint32_t aoff =
        (uint32_t)(warp_m * 32 + (lane & 15)) * (RSH * 2) + ((lane >> 4) << 4);
    const uint32_t boff =
        (uint32_t)(warp_n * 32 + (lane & 7) + ((lane >> 4) << 3)) * (RSH * 2)
        + (((lane >> 3) & 1) << 4);

    const int NK = K >> 6;
    load_stage(0, 0);
    load_stage(1, 1);

    for (int it = 0; it < NK; it++) {
        if (it + 1 < NK)
            asm volatile("cp.async.wait_group 1;" ::: "memory");
        else
            asm volatile("cp.async.wait_group 0;" ::: "memory");
        __syncthreads();
        if (it + 2 < NK) load_stage((it + 2) % NSTG, it + 2);

        const uint32_t sA = sbase + (uint32_t)((it % NSTG) * STGB);
        const uint32_t sB = sA + OPB;

        #pragma unroll
        for (int ks = 0; ks < 4; ks++) {
            const uint32_t kb = ks * 32;
            unsigned a[2][4];
            LDSM4(a[0][0], a[0][1], a[0][2], a[0][3], sA + aoff + kb);
            LDSM4(a[1][0], a[1][1], a[1][2], a[1][3],
                  sA + aoff + 16u * (RSH * 2) + kb);
            unsigned b[4][2];
            #pragma unroll
            for (int q = 0; q < 2; q++)
                LDSM4(b[2 * q][0], b[2 * q][1], b[2 * q + 1][0], b[2 * q + 1][1],
                      sB + boff + (uint32_t)(q * 16 * (RSH * 2)) + kb);
            #pragma unroll
            for (int im = 0; im < 2; im++)
                #pragma unroll
                for (int j = 0; j < 4; j++)
                    mma_f16(acc[im][j], a[im], b[j]);
        }
    }

    float* Cf = (float*)Cv;
    __half* Ch = (__half*)Cv;
    #pragma unroll
    for (int im = 0; im < 2; im++) {
        #pragma unroll
        for (int j = 0; j < 4; j++) {
            int r = bm + warp_m * 32 + im * 16 + gid;
            int c = bn + warp_n * 32 + j * 8 + tig * 2;
            #pragma unroll
            for (int half_ = 0; half_ < 2; half_++) {
                int rr = r + half_ * 8;
                float v0 = acc[im][j][half_ * 2 + 0];
                float v1 = acc[im][j][half_ * 2 + 1];
                if (BIAS) { v0 += bias[c]; v1 += bias[c + 1]; }
                if (DOGELU) {
                    v0 = gelu_fast(v0);
                    v1 = gelu_fast(v1);
                }
                if (HALFOUT) {
                    *(__half2*)(Ch + (size_t)rr * N + c) =
                        __floats2half2_rn(v0, v1);
                } else {
                    *(float2*)(Cf + (size_t)rr * N + c) = make_float2(v0, v1);
                }
            }
        }
    }
}

// ---------------------------------------------------------------------------
// Tensor-core fp16 flash attention (64-q blocks, 4 warps, 4 CTAs/SM,
// heavy q-tiles first).
// ---------------------------------------------------------------------------
#define ASTR 72   // smem row stride in halves (144B)

__global__ __launch_bounds__(128, 4) void attn_kernel(
    const __half* __restrict__ qkv, __half* __restrict__ out)
{
    __shared__ __half Qs[64 * ASTR];          // 9216 B
    __shared__ __half KVs[2][2][64 * ASTR];   // 36864 B  [buf][K=0/V=1]

    const int tid = threadIdx.x, lane = tid & 31, w = tid >> 5;
    const int gid = lane >> 2, tig = lane & 3;
    const int qt = (int)gridDim.x - 1 - (int)blockIdx.x;   // heavy tiles first
    const int head = blockIdx.y, batch = blockIdx.z;
    const int qbase = qt * 64;
    const __half* base = qkv + (size_t)batch * S_ * D3_;
    const int hd = head * DH_;

    #pragma unroll
    for (int i = 0; i < 4; i++) {
        int id = tid + i * 128;
        int r = id >> 3, c = (id & 7) * 8;
        cp16(smem_u32(Qs + r * ASTR + c),
             base + (size_t)(qbase + r) * D3_ + hd + c);
    }

    auto load_kv = [&](int buf, int kt) {
        #pragma unroll
        for (int i = 0; i < 4; i++) {
            int id = tid + i * 128;
            int r = id >> 3, c = (id & 7) * 8;
            const __half* krow = base + (size_t)(kt * 64 + r) * D3_;
            cp16(smem_u32(&KVs[buf][0][r * ASTR + c]), krow + D_ + hd + c);
            cp16(smem_u32(&KVs[buf][1][r * ASTR + c]), krow + 2 * D_ + hd + c);
        }
        asm volatile("cp.async.commit_group;" ::: "memory");
    };

    const int ntk = qt + 1;
    load_kv(0, 0);
    asm volatile("cp.async.wait_group 0;" ::: "memory");
    __syncthreads();

    unsigned qf[4][4];
    {
        const uint32_t qaddr = smem_u32(Qs)
            + (uint32_t)(w * 16 + (lane & 15)) * (ASTR * 2) + ((lane >> 4) << 4);
        #pragma unroll
        for (int ks = 0; ks < 4; ks++)
            LDSM4(qf[ks][0], qf[ks][1], qf[ks][2], qf[ks][3], qaddr + 32 * ks);
        const __half2 sc = __float2half2_rn(0.125f);
        #pragma unroll
        for (int ks = 0; ks < 4; ks++)
            #pragma unroll
            for (int i = 0; i < 4; i++) {
                __half2 h = *(__half2*)&qf[ks][i];
                h = __hmul2(h, sc);
                qf[ks][i] = *(unsigned*)&h;
            }
    }

    float m0 = -1e30f, m1 = -1e30f, l0 = 0.f, l1 = 0.f;
    float o[8][4];
    #pragma unroll
    for (int j = 0; j < 8; j++)
        #pragma unroll
        for (int c = 0; c < 4; c++) o[j][c] = 0.f;

    for (int kt = 0; kt < ntk; kt++) {
        const int buf = kt & 1;
        if (kt > 0) {
            asm volatile("cp.async.wait_group 0;" ::: "memory");
            __syncthreads();
        }
        if (kt + 1 < ntk) load_kv(buf ^ 1, kt + 1);

        float s[8][4];
        #pragma unroll
        for (int j = 0; j < 8; j++)
            #pragma unroll
            for (int c = 0; c < 4; c++) s[j][c] = 0.f;

        const uint32_t kaddr = smem_u32(&KVs[buf][0][0])
            + (uint32_t)((lane & 7) + ((lane >> 4) << 3)) * (ASTR * 2)
            + (((lane >> 3) & 1) << 4);
        #pragma unroll
        for (int ks = 0; ks < 4; ks++) {
            unsigned b[8][2];
            #pragma unroll
            for (int q = 0; q < 4; q++)
                LDSM4(b[2 * q][0], b[2 * q][1], b[2 * q + 1][0], b[2 * q + 1][1],
                      kaddr + (uint32_t)(q * 16 * (ASTR * 2)) + 32 * ks);
            #pragma unroll
            for (int j = 0; j < 8; j++)
                mma_f16(s[j], qf[ks], b[j]);
        }

        if (kt == qt) {
            const int rA = w * 16 + gid;
            #pragma unroll
            for (int j = 0; j < 8; j++) {
                int c0 = j * 8 + tig * 2, c1 = c0 + 1;
                if (c0 > rA)     s[j][0] = -1e30f;
                if (c1 > rA)     s[j][1] = -1e30f;
                if (c0 > rA + 8) s[j][2] = -1e30f;
                if (c1 > rA + 8) s[j][3] = -1e30f;
            }
        }

        float mx0 = -1e30f, mx1 = -1e30f;
        #pragma unroll
        for (int j = 0; j < 8; j++) {
            mx0 = fmaxf(mx0, fmaxf(s[j][0], s[j][1]));
            mx1 = fmaxf(mx1, fmaxf(s[j][2], s[j][3]));
        }
        #pragma unroll
        for (int off = 1; off <= 2; off <<= 1) {
            mx0 = fmaxf(mx0, __shfl_xor_sync(0xffffffffu, mx0, off));
            mx1 = fmaxf(mx1, __shfl_xor_sync(0xffffffffu, mx1, off));
        }
        const float mn0 = fmaxf(m0, mx0), mn1 = fmaxf(m1, mx1);
        const float al0 = __expf(m0 - mn0), al1 = __expf(m1 - mn1);
        m0 = mn0; m1 = mn1;

        unsigned pf[8][2];
        float sum0 = 0.f, sum1 = 0.f;
        #pragma unroll
        for (int j = 0; j < 8; j++) {
            float p0 = __expf(s[j][0] - mn0), p1 = __expf(s[j][1] - mn0);
            float p2 = __expf(s[j][2] - mn1), p3 = __expf(s[j][3] - mn1);
            __half2 h01 = __floats2half2_rn(p0, p1);
            __half2 h23 = __floats2half2_rn(p2, p3);
            pf[j][0] = *(unsigned*)&h01;
            pf[j][1] = *(unsigned*)&h23;
            sum0 += p0 + p1; sum1 += p2 + p3;
        }
        #pragma unroll
        for (int off = 1; off <= 2; off <<= 1) {
            sum0 += __shfl_xor_sync(0xffffffffu, sum0, off);
            sum1 += __shfl_xor_sync(0xffffffffu, sum1, off);
        }
        l0 = l0 * al0 + sum0;
        l1 = l1 * al1 + sum1;
        #pragma unroll
        for (int j = 0; j < 8; j++) {
            o[j][0] *= al0; o[j][1] *= al0;
            o[j][2] *= al1; o[j][3] *= al1;
        }

        const uint32_t vaddr = smem_u32(&KVs[buf][1][0])
            + (uint32_t)(lane & 15) * (ASTR * 2) + ((lane >> 4) << 4);
        #pragma unroll
        for (int ks = 0; ks < 4; ks++) {
            unsigned a[4] = { pf[2 * ks][0], pf[2 * ks][1],
                              pf[2 * ks + 1][0], pf[2 * ks + 1][1] };
            unsigned b[8][2];
            #pragma unroll
            for (int q = 0; q < 4; q++)
                LDSM4T(b[2 * q][0], b[2 * q][1], b[2 * q + 1][0], b[2 * q + 1][1],
                       vaddr + (uint32_t)(ks * 16 * (ASTR * 2)) + q * 32);
            #pragma unroll
            for (int j = 0; j < 8; j++)
                mma_f16(o[j], a, b[j]);
        }
    }

    const float inv0 = 1.0f / l0, inv1 = 1.0f / l1;
    const int row0 = batch * S_ + qbase + w * 16 + gid;
    #pragma unroll
    for (int j = 0; j < 8; j++) {
        int col = hd + j * 8 + tig * 2;
        *(__half2*)(out + (size_t)row0 * D_ + col) =
            __floats2half2_rn(o[j][0] * inv0, o[j][1] * inv0);
        *(__half2*)(out + (size_t)(row0 + 8) * D_ + col) =
            __floats2half2_rn(o[j][2] * inv1, o[j][3] * inv1);
    }
}

// ---------------------------------------------------------------------------
// Warp-per-row fused LayerNorm: row = hp0 + hp1 + bias + res (fp16 split-K
// partial reduction), then LN with gamma/beta; writes fp32 out + fp16 copy.
// One warp per row, 8 rows per 256-thread block, no barriers, shfl reductions.
// Each lane holds 24 values (6 x float4 strided) in registers.
// ---------------------------------------------------------------------------
__global__ __launch_bounds__(256) void ln_red_kernel(
    const __half* __restrict__ hp0, const __half* __restrict__ hp1,
    const float* __restrict__ bias, const float* __restrict__ res,
    const float* __restrict__ g, const float* __restrict__ b,
    float* __restrict__ out, __half* __restrict__ outh)
{
    const int warp = threadIdx.x >> 5, lane = threadIdx.x & 31;
    const size_t rb = (size_t)(blockIdx.x * 8 + warp) * D_;

    float v[24];
    #pragma unroll
    for (int i = 0; i < 6; i++) {
        const int c = (i * 32 + lane) * 4;
        float2 a0 = __half22float2(*(const __half2*)(hp0 + rb + c));
        float2 a1 = __half22float2(*(const __half2*)(hp0 + rb + c + 2));
        float2 b0 = __half22float2(*(const __half2*)(hp1 + rb + c));
        float2 b1 = __half22float2(*(const __half2*)(hp1 + rb + c + 2));
        float4 bs = *(const float4*)(bias + c);
        float4 rs = *(const float4*)(res + rb + c);
        v[4 * i + 0] = a0.x + b0.x + bs.x + rs.x;
        v[4 * i + 1] = a0.y + b0.y + bs.y + rs.y;
        v[4 * i + 2] = a1.x + b1.x + bs.z + rs.z;
        v[4 * i + 3] = a1.y + b1.y + bs.w + rs.w;
    }

    float s = 0.f;
    #pragma unroll
    for (int k = 0; k < 24; k++) s += v[k];
    #pragma unroll
    for (int off = 16; off > 0; off >>= 1)
        s += __shfl_xor_sync(0xffffffffu, s, off);
    const float mean = s * (1.0f / D_);

    float q = 0.f;
    #pragma unroll
    for (int k = 0; k < 24; k++) { v[k] -= mean; q += v[k] * v[k]; }
    #pragma unroll
    for (int off = 16; off > 0; off >>= 1)
        q += __shfl_xor_sync(0xffffffffu, q, off);
    const float rstd = rsqrtf(q * (1.0f / D_) + 1e-5f);

    #pragma unroll
    for (int i = 0; i < 6; i++) {
        const int c = (i * 32 + lane) * 4;
        float4 gv = *(const float4*)(g + c);
        float4 bv = *(const float4*)(b + c);
        float y0 = v[4 * i + 0] * rstd * gv.x + bv.x;
        float y1 = v[4 * i + 1] * rstd * gv.y + bv.y;
        float y2 = v[4 * i + 2] * rstd * gv.z + bv.z;
        float y3 = v[4 * i + 3] * rstd * gv.w + bv.w;
        *(float4*)(out + rb + c) = make_float4(y0, y1, y2, y3);
        *(__half2*)(outh + rb + c)     = __floats2half2_rn(y0, y1);
        *(__half2*)(outh + rb + c + 2) = __floats2half2_rn(y2, y3);
    }
}

// ---------------------------------------------------------------------------
// Launch
// ---------------------------------------------------------------------------
extern "C" void kernel_launch(void* const* d_in, const int* in_sizes, int n_in,
                              void* d_out, int out_size)
{
    (void)in_sizes; (void)n_in; (void)out_size;

    const void*  x           = d_in[0];
    const float* we          = (const float*)d_in[1];
    const float* c_attn_w    = (const float*)d_in[2];
    const float* c_attn_b    = (const float*)d_in[3];
    const float* attn_proj_w = (const float*)d_in[4];
    const float* attn_proj_b = (const float*)d_in[5];
    const float* ln1_g       = (const float*)d_in[6];
    const float* ln1_b       = (const float*)d_in[7];
    const float* fc_w        = (const float*)d_in[8];
    const float* fc_b        = (const float*)d_in[9];
    const float* mlp_proj_w  = (const float*)d_in[10];
    const float* mlp_proj_b  = (const float*)d_in[11];
    const float* ln2_g       = (const float*)d_in[12];
    const float* ln2_b       = (const float*)d_in[13];
    float* out = (float*)d_out;

    float *nbuf;
    __half *qkv, *attnb, *nr, *hr, *ff, *p2h;
    __half *cawT, *apwT, *fcwT, *mpwT;
    cudaGetSymbolAddress((void**)&qkv,   g_qkv);
    cudaGetSymbolAddress((void**)&attnb, g_attn);
    cudaGetSymbolAddress((void**)&nbuf,  g_n);
    cudaGetSymbolAddress((void**)&nr,    g_nr);
    cudaGetSymbolAddress((void**)&hr,    g_hr);
    cudaGetSymbolAddress((void**)&ff,    g_ff);
    cudaGetSymbolAddress((void**)&p2h,   g_p2);
    cudaGetSymbolAddress((void**)&cawT,  g_caw_t);
    cudaGetSymbolAddress((void**)&apwT,  g_apw_t);
    cudaGetSymbolAddress((void**)&fcwT,  g_fcw_t);
    cudaGetSymbolAddress((void**)&mpwT,  g_mpw_t);

    // GEMM variants:
    //   qkv: bias, fp16 out
    //   fc : bias+gelu, fp16 out
    //   split-K (proj & mlp): raw fp16 partials, reduction fused into LN
    cudaFuncSetAttribute(mma_gemm_kernel<true, false, true, false>,
                         cudaFuncAttributeMaxDynamicSharedMemorySize, GEMM_SMEM);
    cudaFuncSetAttribute(mma_gemm_kernel<true, true, true, false>,
                         cudaFuncAttributeMaxDynamicSharedMemorySize, GEMM_SMEM);
    cudaFuncSetAttribute(mma_gemm_kernel<false, false, true, true>,
                         cudaFuncAttributeMaxDynamicSharedMemorySize, GEMM_SMEM);

    // Single prep launch: embedding + all weight transposes.
    prep_kernel<<<NB_PREP, 256>>>(x, we, out, hr,
                                  c_attn_w, cawT, attn_proj_w, apwT,
                                  fc_w, fcwT, mlp_proj_w, mpwT);

    for (int l = 0; l < L_; l++) {
        const float* h    = out + (size_t)l * BS_ * D_;
        float*       hout = out + (size_t)(l + 1) * BS_ * D_;

        // qkv = h @ caw + cab   (fp16 out)
        mma_gemm_kernel<true, false, true, false>
            <<<dim3(D3_ / 128, BS_ / 128), GTHREADS, GEMM_SMEM>>>(
            hr, cawT + (size_t)l * D3_ * D_, c_attn_b + (size_t)l * D3_,
            qkv, BS_, D3_, D_);

        // a = causal_attention(qkv)  (tensor-core, fp16 out)
        attn_kernel<<<dim3(S_ / 64, H_, B_), 128>>>(qkv, attnb);

        // proj partials (fp16 split-K): p2[z] = a[:, z-half] @ apw[z-half]
        mma_gemm_kernel<false, false, true, true>
            <<<dim3(D_ / 128, BS_ / 128, 2), GTHREADS, GEMM_SMEM>>>(
            attnb, apwT + (size_t)l * D_ * D_, nullptr,
            p2h, BS_, D_, D_ / 2);

        // n = LN(p0 + p1 + apb + h)  (+ fp16 copy for fc A)
        ln_red_kernel<<<BS_ / 8, 256>>>(p2h, p2h + (size_t)BS_ * D_,
                                        attn_proj_b + (size_t)l * D_, h,
                                        ln1_g + (size_t)l * D_,
                                        ln1_b + (size_t)l * D_, nbuf, nr);

        // ff = gelu(n @ fw + fb)  (fp16 out)
        mma_gemm_kernel<true, true, true, false>
            <<<dim3(FF_ / 128, BS_ / 128), GTHREADS, GEMM_SMEM>>>(
            nr, fcwT + (size_t)l * FF_ * D_, fc_b + (size_t)l * FF_,
            ff, BS_, FF_, D_);

        // mlp partials (fp16 split-K): p2[z] = ff[:, z-half] @ pw[z-half]
        mma_gemm_kernel<false, false, true, true>
            <<<dim3(D_ / 128, BS_ / 128, 2), GTHREADS, GEMM_SMEM>>>(
            ff, mpwT + (size_t)l * D_ * FF_, nullptr,
            p2h, BS_, D_, FF_ / 2);

        // out_{l+1} = LN(p0 + p1 + pb + n)  (+ fp16 copy for next qkv A)
        ln_red_kernel<<<BS_ / 8, 256>>>(p2h, p2h + (size_t)BS_ * D_,
                                        mlp_proj_b + (size_t)l * D_, nbuf,
                                        ln2_g + (size_t)l * D_,
                                        ln2_b + (size_t)l * D_, hout, hr);
    }
}